// round 6
// baseline (speedup 1.0000x reference)
#include <cuda_runtime.h>
#include <stdint.h>

// Dataset constants (fast path speculates on these; general path stays correct)
#define NN2  361
#define MM   361
#define HASH_SLOTS 1024
#define HASH_MASK  1023
#define NT   256
#define G_UNI 8      // groups per board (uniform CSR guess)
#define S_UNI 16     // stones per group (uniform CSR guess)
#define NST_UNI (G_UNI * S_UNI)   // 128
#define MAXG  64
#define MAXST 512

__device__ __forceinline__ unsigned hash_fn(int v) {
    return (((unsigned)v) * 2654435761u) >> 22;   // top 10 bits -> [0,1024)
}

__device__ __forceinline__ void hset_insert(int* hset, int v) {
    unsigned h = hash_fn(v) & HASH_MASK;
    while (true) {
        int prev = atomicCAS(&hset[h], -1, v);
        if (prev == -1 || prev == v) break;
        h = (h + 1) & HASH_MASK;
    }
}

__global__ __launch_bounds__(NT)
void superko_kernel(const int* __restrict__ ZposT,           // [3, N2]
                    const int* __restrict__ current_player,  // [B]
                    const int* __restrict__ current_hash,    // [B]
                    const int* __restrict__ hash_history,    // [B, M]
                    const int* __restrict__ move_count,      // [B]
                    const int* __restrict__ legal,           // [B, N2] bool (4B)
                    const int* __restrict__ sidx,            // [K]
                    const int* __restrict__ sptr,            // [R+1]
                    const int* __restrict__ gptr,            // [B+1]
                    const int* __restrict__ cap,             // [B, N2, 4]
                    float* __restrict__ out,                 // [B, N2] bool-as-f32
                    int K, int R)
{
    __shared__ int hset[HASH_SLOTS];
    __shared__ int gxor[MAXG];
    __shared__ int sdelta[MAXST];   // slow (general) path only
    __shared__ int sflag;

    const int b   = blockIdx.x;
    const int tid = threadIdx.x;

    // ================= t0: fire all independent loads =================
    const int player = __ldg(&current_player[b]);
    int mc           = __ldg(&move_count[b]);
    const int ch     = __ldg(&current_hash[b]);
    if (mc > MM) mc = MM;
    if (mc < 0)  mc = 0;

    const int4* cap4 = (const int4*)(cap + (long long)b * NN2 * 4);
    const int*  lg   = legal + (long long)b * NN2;
    const int*  hist = hash_history + (long long)b * MM;

    const int j0 = tid, j1 = tid + NT;
    const bool has1 = (j1 < NN2);

    // cell 0 (always valid): placement-delta inputs, both colors (no player dep)
    int4 c4_0 = cap4[j0];
    int  lg_0 = lg[j0];
    int  ze0 = ZposT[j0], zb0 = ZposT[NN2 + j0], zw0 = ZposT[2 * NN2 + j0];
    // cell 1
    int4 c4_1 = make_int4(-1, -1, -1, -1);
    int  lg_1 = 0, ze1 = 0, zb1 = 0, zw1 = 0;
    if (has1) {
        c4_1 = cap4[j1];
        lg_1 = lg[j1];
        ze1 = ZposT[j1]; zb1 = ZposT[NN2 + j1]; zw1 = ZposT[2 * NN2 + j1];
    }

    // history prefetch
    int hv0 = hist[j0];
    int hv1 = has1 ? hist[j1] : 0;

    // speculative stone gather: guess stone_base = 128*b
    int sze = 0, szb = 0, szw = 0;
    if (tid < NST_UNI) {
        int idx = NST_UNI * b + tid;
        if (idx >= K) idx = K - 1;           // bounds-safe even if guess is wrong
        int c = sidx[idx];
        sze = ZposT[c]; szb = ZposT[NN2 + c]; szw = ZposT[2 * NN2 + c];
    }

    // verification loads (warp 0): is the CSR the uniform layout?
    bool ok = true;
    if (tid < 32) {
        if (tid <= G_UNI) {
            int gi = G_UNI * b + tid;
            int sv = (gi <= R) ? sptr[gi] : -1;
            ok = (sv == S_UNI * gi);
        }
        if (tid == 0) ok = ok && (gptr[b] == G_UNI * b);
        if (tid == 1) ok = ok && (gptr[b + 1] == G_UNI * (b + 1));
        unsigned m = __ballot_sync(0xffffffffu, ok);
        if (tid == 0) sflag = (m == 0xffffffffu) ? 1 : 0;
    }

    // hash set init: one STS.128 per thread (1024 slots / 4)
    ((int4*)hset)[tid] = make_int4(-1, -1, -1, -1);

    // speculative group XOR: 16-lane butterfly reduce (warps 0-3 fully active)
    if (tid < NST_UNI) {
        int d = sze ^ ((player == 0) ? szw : szb);   // opponent color removal delta
        d ^= __shfl_xor_sync(0xffffffffu, d, 8);
        d ^= __shfl_xor_sync(0xffffffffu, d, 4);
        d ^= __shfl_xor_sync(0xffffffffu, d, 2);
        d ^= __shfl_xor_sync(0xffffffffu, d, 1);
        if ((tid & (S_UNI - 1)) == 0) gxor[tid >> 4] = d;
    }

    __syncthreads();   // barrier 1: hset initialized, sflag visible

    // ================= inserts =================
    if (j0 < mc) hset_insert(hset, hv0);
    if (j1 < mc) hset_insert(hset, hv1);

    // ================= general fallback (never taken on this dataset) =================
    if (!sflag) {
        int gstart = gptr[b];
        int ng = gptr[b + 1] - gstart;
        if (ng < 0) ng = 0; if (ng > MAXG) ng = MAXG;
        int sbase = sptr[gstart];
        int nst = sptr[gstart + ng] - sbase;
        if (nst < 0) nst = 0; if (nst > MAXST) nst = MAXST;
        const int* zoRow = ZposT + ((player == 0) ? 2 * NN2 : NN2);
        for (int s = tid; s < nst; s += NT) {
            int c = sidx[sbase + s];
            sdelta[s] = ZposT[c] ^ zoRow[c];
        }
        __syncthreads();
        if (tid < ng) {
            int s0 = sptr[gstart + tid] - sbase;
            int s1 = sptr[gstart + tid + 1] - sbase;
            if (s0 < 0) s0 = 0; if (s1 > nst) s1 = nst;
            int x = 0;
            for (int s = s0; s < s1; ++s) x ^= sdelta[s];
            gxor[tid] = x;
        }
    }

    __syncthreads();   // barrier 2: hset populated, gxor final

    // ================= probes + output =================
    float* ob = out + (long long)b * NN2;

    {
        int cd = 0;
        if (c4_0.x >= 0) cd ^= gxor[c4_0.x];
        if (c4_0.y >= 0) cd ^= gxor[c4_0.y];
        if (c4_0.z >= 0) cd ^= gxor[c4_0.z];
        if (c4_0.w >= 0) cd ^= gxor[c4_0.w];
        int pd = ze0 ^ ((player == 0) ? zb0 : zw0);
        int cand = ch ^ pd ^ cd;
        bool found = false;
        unsigned h = hash_fn(cand) & HASH_MASK;
        while (true) {
            int v = hset[h];
            if (v == -1) break;
            if (v == cand) { found = true; break; }
            h = (h + 1) & HASH_MASK;
        }
        ob[j0] = (lg_0 != 0 && !found) ? 1.0f : 0.0f;
    }
    if (has1) {
        int cd = 0;
        if (c4_1.x >= 0) cd ^= gxor[c4_1.x];
        if (c4_1.y >= 0) cd ^= gxor[c4_1.y];
        if (c4_1.z >= 0) cd ^= gxor[c4_1.z];
        if (c4_1.w >= 0) cd ^= gxor[c4_1.w];
        int pd = ze1 ^ ((player == 0) ? zb1 : zw1);
        int cand = ch ^ pd ^ cd;
        bool found = false;
        unsigned h = hash_fn(cand) & HASH_MASK;
        while (true) {
            int v = hset[h];
            if (v == -1) break;
            if (v == cand) { found = true; break; }
            h = (h + 1) & HASH_MASK;
        }
        ob[j1] = (lg_1 != 0 && !found) ? 1.0f : 0.0f;
    }
}

extern "C" void kernel_launch(void* const* d_in, const int* in_sizes, int n_in,
                              void* d_out, int out_size) {
    const int* ZposT        = (const int*)d_in[0];
    const int* cur_player   = (const int*)d_in[1];
    const int* cur_hash     = (const int*)d_in[2];
    const int* hash_hist    = (const int*)d_in[3];
    const int* mv_count     = (const int*)d_in[4];
    const int* lg           = (const int*)d_in[5];
    const int* sidx         = (const int*)d_in[6];
    const int* sptr         = (const int*)d_in[7];
    const int* gptr         = (const int*)d_in[8];
    const int* cap          = (const int*)d_in[9];
    // d_in[10] = scale (unused by the reference output)

    float* out = (float*)d_out;
    const int B = in_sizes[8] - 1;     // gptr has B+1 entries
    const int K = in_sizes[6];
    const int R = in_sizes[7] - 1;

    superko_kernel<<<B, NT>>>(ZposT, cur_player, cur_hash, hash_hist,
                              mv_count, lg, sidx, sptr, gptr, cap, out, K, R);
}